// round 1
// baseline (speedup 1.0000x reference)
#include <cuda_runtime.h>
#include <math.h>

#define BB 8
#define TB 256
#define SB 256
#define HH 512

// Scratch (static device globals -- allowed; no runtime allocation)
__device__ float g_WsQ[BB * TB * HH];   // 4 MB
__device__ float g_WhE[BB * SB * HH];   // 4 MB
__device__ float g_attn[BB * TB * SB];  // 2 MB
__device__ float g_ctx[BB * TB * HH];   // 4 MB

typedef unsigned long long u64;

__device__ __forceinline__ u64 pack2(float lo, float hi) {
    u64 r; asm("mov.b64 %0,{%1,%2};" : "=l"(r) : "f"(lo), "f"(hi)); return r;
}
__device__ __forceinline__ void unpack2(u64 p, float& lo, float& hi) {
    asm("mov.b64 {%0,%1},%2;" : "=f"(lo), "=f"(hi) : "l"(p));
}
__device__ __forceinline__ u64 ffma2(u64 a, u64 b, u64 c) {
    u64 d; asm("fma.rn.f32x2 %0,%1,%2,%3;" : "=l"(d) : "l"(a), "l"(b), "l"(c)); return d;
}
__device__ __forceinline__ float tanhfast(float x) {
    float y; asm("tanh.approx.f32 %0, %1;" : "=f"(y) : "f"(x)); return y;
}

// ---------------------------------------------------------------------------
// NT GEMM: C[n][m] = sum_k Asrc[n][k] * W[m][k]
// Asrc = A for k < 512-split (or always, if A2 == nullptr), A2 for k >= 512.
// 64x64 tile, KC=16, 256 threads, 4x4 micro-tile via fma.rn.f32x2.
// EPI=1 applies accurate tanhf at store.
// ---------------------------------------------------------------------------
template <int EPI>
__global__ void __launch_bounds__(256) gemm_nt_kernel(
    const float* __restrict__ A, const float* __restrict__ A2,
    const float* __restrict__ W, float* __restrict__ C,
    int M, int K, int lda, int ldw)
{
    __shared__ float As[16][68];
    __shared__ float Ws[16][68];
    const int tid = threadIdx.x;
    const int tx = tid & 15, ty = tid >> 4;
    const int n0 = blockIdx.y * 64, m0 = blockIdx.x * 64;

    u64 acc[4][2];
#pragma unroll
    for (int i = 0; i < 4; i++) { acc[i][0] = 0ull; acc[i][1] = 0ull; }

    const int lrow = tid >> 2;           // 0..63
    const int lk4  = (tid & 3) << 2;     // 0,4,8,12

    for (int k0 = 0; k0 < K; k0 += 16) {
        const float* Ap = A; int kc = k0;
        if (A2 != nullptr && k0 >= 512) { Ap = A2; kc = k0 - 512; }

        float4 av = *(const float4*)&Ap[(size_t)(n0 + lrow) * lda + kc + lk4];
        As[lk4 + 0][lrow] = av.x; As[lk4 + 1][lrow] = av.y;
        As[lk4 + 2][lrow] = av.z; As[lk4 + 3][lrow] = av.w;
        float4 wv = *(const float4*)&W[(size_t)(m0 + lrow) * ldw + k0 + lk4];
        Ws[lk4 + 0][lrow] = wv.x; Ws[lk4 + 1][lrow] = wv.y;
        Ws[lk4 + 2][lrow] = wv.z; Ws[lk4 + 3][lrow] = wv.w;
        __syncthreads();

#pragma unroll
        for (int kk = 0; kk < 16; kk++) {
            float4 a4 = *(const float4*)&As[kk][ty << 2];
            ulonglong2 b2 = *(const ulonglong2*)&Ws[kk][tx << 2];
            u64 aa;
            aa = pack2(a4.x, a4.x);
            acc[0][0] = ffma2(aa, b2.x, acc[0][0]); acc[0][1] = ffma2(aa, b2.y, acc[0][1]);
            aa = pack2(a4.y, a4.y);
            acc[1][0] = ffma2(aa, b2.x, acc[1][0]); acc[1][1] = ffma2(aa, b2.y, acc[1][1]);
            aa = pack2(a4.z, a4.z);
            acc[2][0] = ffma2(aa, b2.x, acc[2][0]); acc[2][1] = ffma2(aa, b2.y, acc[2][1]);
            aa = pack2(a4.w, a4.w);
            acc[3][0] = ffma2(aa, b2.x, acc[3][0]); acc[3][1] = ffma2(aa, b2.y, acc[3][1]);
        }
        __syncthreads();
    }

#pragma unroll
    for (int i = 0; i < 4; i++) {
        float c0, c1, c2, c3;
        unpack2(acc[i][0], c0, c1);
        unpack2(acc[i][1], c2, c3);
        if (EPI) { c0 = tanhf(c0); c1 = tanhf(c1); c2 = tanhf(c2); c3 = tanhf(c3); }
        float4 o = make_float4(c0, c1, c2, c3);
        *(float4*)&C[(size_t)(n0 + (ty << 2) + i) * M + m0 + (tx << 2)] = o;
    }
}

// ---------------------------------------------------------------------------
// NN batched GEMM (context): C[b][t][h] = sum_s attn[b][t][s] * enc[b][s][h]
// ---------------------------------------------------------------------------
__global__ void __launch_bounds__(256) gemm_nn_kernel(const float* __restrict__ enc)
{
    __shared__ float As[16][68];  // [s][t]
    __shared__ float Bs[16][68];  // [s][h]
    const int tid = threadIdx.x;
    const int tx = tid & 15, ty = tid >> 4;
    const int b = blockIdx.z;
    const int t0 = blockIdx.y * 64, h0 = blockIdx.x * 64;
    const float* A  = g_attn + (size_t)b * TB * SB;
    const float* Bm = enc    + (size_t)b * SB * HH;
    float* C        = g_ctx  + (size_t)b * TB * HH;

    u64 acc[4][2];
#pragma unroll
    for (int i = 0; i < 4; i++) { acc[i][0] = 0ull; acc[i][1] = 0ull; }

    const int lrowA = tid >> 2;
    const int lk4A  = (tid & 3) << 2;
    const int lrowB = tid >> 4;          // 0..15
    const int lc4B  = (tid & 15) << 2;   // 0..60

    for (int k0 = 0; k0 < SB; k0 += 16) {
        float4 av = *(const float4*)&A[(size_t)(t0 + lrowA) * SB + k0 + lk4A];
        As[lk4A + 0][lrowA] = av.x; As[lk4A + 1][lrowA] = av.y;
        As[lk4A + 2][lrowA] = av.z; As[lk4A + 3][lrowA] = av.w;
        float4 bv = *(const float4*)&Bm[(size_t)(k0 + lrowB) * HH + h0 + lc4B];
        *(float4*)&Bs[lrowB][lc4B] = bv;
        __syncthreads();

#pragma unroll
        for (int kk = 0; kk < 16; kk++) {
            float4 a4 = *(const float4*)&As[kk][ty << 2];
            ulonglong2 b2 = *(const ulonglong2*)&Bs[kk][tx << 2];
            u64 aa;
            aa = pack2(a4.x, a4.x);
            acc[0][0] = ffma2(aa, b2.x, acc[0][0]); acc[0][1] = ffma2(aa, b2.y, acc[0][1]);
            aa = pack2(a4.y, a4.y);
            acc[1][0] = ffma2(aa, b2.x, acc[1][0]); acc[1][1] = ffma2(aa, b2.y, acc[1][1]);
            aa = pack2(a4.z, a4.z);
            acc[2][0] = ffma2(aa, b2.x, acc[2][0]); acc[2][1] = ffma2(aa, b2.y, acc[2][1]);
            aa = pack2(a4.w, a4.w);
            acc[3][0] = ffma2(aa, b2.x, acc[3][0]); acc[3][1] = ffma2(aa, b2.y, acc[3][1]);
        }
        __syncthreads();
    }

#pragma unroll
    for (int i = 0; i < 4; i++) {
        float c0, c1, c2, c3;
        unpack2(acc[i][0], c0, c1);
        unpack2(acc[i][1], c2, c3);
        float4 o = make_float4(c0, c1, c2, c3);
        *(float4*)&C[(size_t)(t0 + (ty << 2) + i) * HH + h0 + (tx << 2)] = o;
    }
}

// ---------------------------------------------------------------------------
// Fused energies + masked softmax.
// Block = (b, 16 t-rows). 256 threads: tt = tid/16 (t), sx = tid%16 (s lane).
// e[b,t,s] = sum_h v[h] * tanh(WsQ[b,t,h] + WhE[b,s,h]); mask s >= len -> 0.
// ---------------------------------------------------------------------------
__global__ void __launch_bounds__(256) attn_energy_softmax(
    const int* __restrict__ lens, const float* __restrict__ v)
{
    __shared__ float sA[16][513];  // WsQ tile [t][h], full H
    __shared__ float sB[16][129];  // WhE chunk [s][h_sub=128]
    __shared__ float sV[HH];

    const int b  = blockIdx.y;
    const int t0 = blockIdx.x << 4;
    const int tid = threadIdx.x;
    const int sx = tid & 15, tt = tid >> 4;

    // load sA: 16 rows x 512 floats = 2048 float4
    for (int i = tid; i < 2048; i += 256) {
        int row = i >> 7, c4 = (i & 127) << 2;
        float4 val = *(const float4*)&g_WsQ[((size_t)(b * TB + t0 + row)) * HH + c4];
        sA[row][c4 + 0] = val.x; sA[row][c4 + 1] = val.y;
        sA[row][c4 + 2] = val.z; sA[row][c4 + 3] = val.w;
    }
    for (int i = tid; i < HH; i += 256) sV[i] = v[i];
    __syncthreads();

    float e[16];

    for (int c = 0; c < 16; c++) {
        float acc = 0.f;
        for (int hc = 0; hc < 4; hc++) {
            __syncthreads();  // previous sB consumers done
            // load sB: 16 s-rows x 128 floats = 512 float4
            for (int i = tid; i < 512; i += 256) {
                int row = i >> 5, c4 = (i & 31) << 2;
                float4 val = *(const float4*)
                    &g_WhE[((size_t)(b * SB + (c << 4) + row)) * HH + (hc << 7) + c4];
                sB[row][c4 + 0] = val.x; sB[row][c4 + 1] = val.y;
                sB[row][c4 + 2] = val.z; sB[row][c4 + 3] = val.w;
            }
            __syncthreads();

            const float* ar = &sA[tt][hc << 7];
            const float* br = &sB[sx][0];
            const float* vr = &sV[hc << 7];
#pragma unroll 8
            for (int h = 0; h < 128; h++)
                acc = fmaf(vr[h], tanhfast(ar[h] + br[h]), acc);
        }
        e[c] = acc;
    }

    // masked softmax over s (row = 16 lanes of same tt, aligned 16-lane group)
    const int len = lens[b];
    float m = -3.0e38f;
#pragma unroll
    for (int c = 0; c < 16; c++) {
        int s = (c << 4) + sx;
        if (s < len) m = fmaxf(m, e[c]);
    }
#pragma unroll
    for (int o = 8; o; o >>= 1) m = fmaxf(m, __shfl_xor_sync(0xffffffffu, m, o));

    float sum = 0.f;
#pragma unroll
    for (int c = 0; c < 16; c++) {
        int s = (c << 4) + sx;
        float w = (s < len) ? __expf(e[c] - m) : 0.f;
        e[c] = w;
        sum += w;
    }
#pragma unroll
    for (int o = 8; o; o >>= 1) sum += __shfl_xor_sync(0xffffffffu, sum, o);
    float inv = 1.f / sum;

#pragma unroll
    for (int c = 0; c < 16; c++)
        g_attn[((size_t)(b * TB + t0 + tt)) * SB + (c << 4) + sx] = e[c] * inv;
}

// ---------------------------------------------------------------------------

extern "C" void kernel_launch(void* const* d_in, const int* in_sizes, int n_in,
                              void* d_out, int out_size)
{
    (void)in_sizes; (void)n_in; (void)out_size;
    const float* query = (const float*)d_in[0];  // (B,T,H)
    const float* enc   = (const float*)d_in[1];  // (B,S,H)
    const int*   lens  = (const int*)d_in[2];    // (B,)
    const float* W_s   = (const float*)d_in[3];  // (H,H)
    const float* W_h   = (const float*)d_in[4];  // (H,H)
    const float* v     = (const float*)d_in[5];  // (H,)
    const float* W_out = (const float*)d_in[6];  // (H,2H)
    float* out = (float*)d_out;                  // (B,T,H)

    float *pWsQ, *pWhE, *pCtx;
    cudaGetSymbolAddress((void**)&pWsQ, g_WsQ);
    cudaGetSymbolAddress((void**)&pWhE, g_WhE);
    cudaGetSymbolAddress((void**)&pCtx, g_ctx);

    dim3 thr(256);
    // 1) WsQ = query @ W_s^T : N=2048, M=512, K=512
    gemm_nt_kernel<0><<<dim3(8, 32), thr>>>(query, nullptr, W_s, pWsQ, 512, 512, 512, 512);
    // 2) WhE = enc @ W_h^T
    gemm_nt_kernel<0><<<dim3(8, 32), thr>>>(enc, nullptr, W_h, pWhE, 512, 512, 512, 512);
    // 3) energies + masked softmax -> g_attn
    attn_energy_softmax<<<dim3(TB / 16, BB), thr>>>(lens, v);
    // 4) context = attn @ enc (batched)
    gemm_nn_kernel<<<dim3(HH / 64, TB / 64, BB), thr>>>(enc);
    // 5) out = tanh([ctx, query] @ W_out^T) : K=1024 concat split at 512
    gemm_nt_kernel<1><<<dim3(8, 32), thr>>>(pCtx, query, W_out, out, 512, 1024, 512, 1024);
}

// round 3
// speedup vs baseline: 1.3792x; 1.3792x over previous
#include <cuda_runtime.h>
#include <cuda_bf16.h>
#include <cstdint>
#include <math.h>

#define BB 8
#define TB 256
#define SB 256
#define HH 512

// ---------------------------------------------------------------------------
// Static device scratch (no runtime allocation)
// ---------------------------------------------------------------------------
__device__ float g_WsQ[BB * TB * HH];   // 4 MB
__device__ float g_WhE[BB * SB * HH];   // 4 MB
__device__ float g_attn[BB * TB * SB];  // 2 MB
__device__ float g_ctx[BB * TB * HH];   // 4 MB

// bf16 3-term split buffers: A-style = [hi, lo, hi], B-style = [hi, hi, lo]
__device__ __nv_bfloat16 g_qA[2048 * 1536];
__device__ __nv_bfloat16 g_eA[2048 * 1536];
__device__ __nv_bfloat16 g_Ws3[512 * 1536];
__device__ __nv_bfloat16 g_Wh3[512 * 1536];
__device__ __nv_bfloat16 g_Wo3[512 * 3072];
__device__ __nv_bfloat16 g_A5[2048 * 3072];

typedef unsigned long long u64;

__device__ __forceinline__ uint32_t smem_u32(const void* p) {
    uint32_t a;
    asm("{ .reg .u64 t; cvta.to.shared.u64 t, %1; cvt.u32.u64 %0, t; }" : "=r"(a) : "l"(p));
    return a;
}
__device__ __forceinline__ float tanhfast(float x) {
    float y; asm("tanh.approx.f32 %0, %1;" : "=f"(y) : "f"(x)); return y;
}

// ---------------------------------------------------------------------------
// fp32 -> bf16 hi/lo split conversion kernels
// ---------------------------------------------------------------------------
__device__ __forceinline__ void bfsplit(float x, __nv_bfloat16& h, __nv_bfloat16& l) {
    h = __float2bfloat16(x);
    l = __float2bfloat16(x - __bfloat162float(h));
}

// A-style: out[r*3K + k]=h, +K=l, +2K=h
__global__ void conv3a(const float* __restrict__ X, __nv_bfloat16* __restrict__ O, int K) {
    int idx = blockIdx.x * 256 + threadIdx.x;
    int r = idx / K, k = idx - r * K;
    __nv_bfloat16 h, l; bfsplit(X[idx], h, l);
    size_t base = (size_t)r * 3 * K + k;
    O[base] = h; O[base + K] = l; O[base + 2 * K] = h;
}
// B-style (weights): out[r*3K + k]=h, +K=h, +2K=l
__global__ void conv3b(const float* __restrict__ X, __nv_bfloat16* __restrict__ O, int K) {
    int idx = blockIdx.x * 256 + threadIdx.x;
    int r = idx / K, k = idx - r * K;
    __nv_bfloat16 h, l; bfsplit(X[idx], h, l);
    size_t base = (size_t)r * 3 * K + k;
    O[base] = h; O[base + K] = h; O[base + 2 * K] = l;
}
// concat(ctx, query) A-style split, K=1024 -> K'=3072
__global__ void conv3cat(const float* __restrict__ ctx, const float* __restrict__ q,
                         __nv_bfloat16* __restrict__ O) {
    int idx = blockIdx.x * 256 + threadIdx.x;   // over 2048*1024
    int r = idx >> 10, k = idx & 1023;
    float x = (k < 512) ? ctx[(r << 9) + k] : q[(r << 9) + k - 512];
    __nv_bfloat16 h, l; bfsplit(x, h, l);
    size_t base = (size_t)r * 3072 + k;
    O[base] = h; O[base + 1024] = l; O[base + 2048] = h;
}

// ---------------------------------------------------------------------------
// HMMA GEMM: C[row][col] = sum_k A[row][k] * B[col][k]  (bf16 K-major both)
// mma.sync.m16n8k16 bf16, 128x64 block tile, 8 warps of 32x32, K-chunk 32.
// ---------------------------------------------------------------------------
__device__ __forceinline__ void mma16816(float* c, const uint32_t* a, const uint32_t* b) {
    asm volatile(
        "mma.sync.aligned.m16n8k16.row.col.f32.bf16.bf16.f32 "
        "{%0,%1,%2,%3}, {%4,%5,%6,%7}, {%8,%9}, {%0,%1,%2,%3};"
        : "+f"(c[0]), "+f"(c[1]), "+f"(c[2]), "+f"(c[3])
        : "r"(a[0]), "r"(a[1]), "r"(a[2]), "r"(a[3]), "r"(b[0]), "r"(b[1]));
}

template <int EPI>
__global__ void __launch_bounds__(256) hmma_gemm(
    const __nv_bfloat16* __restrict__ A, const __nv_bfloat16* __restrict__ B,
    float* __restrict__ C, int Kp, int ldc)
{
    __shared__ __align__(16) __nv_bfloat16 As[128][40];  // pitch 80B: conflict-free ldmatrix
    __shared__ __align__(16) __nv_bfloat16 Bs[64][40];

    const int tid = threadIdx.x, wid = tid >> 5, lane = tid & 31;
    const int row0 = blockIdx.y * 128, col0 = blockIdx.x * 64;
    const int wm = wid & 3, wn = wid >> 2;

    float acc[2][4][4];
#pragma unroll
    for (int mt = 0; mt < 2; mt++)
#pragma unroll
        for (int nt = 0; nt < 4; nt++)
#pragma unroll
            for (int i = 0; i < 4; i++) acc[mt][nt][i] = 0.f;

    // ldmatrix smem addresses (fixed per thread)
    uint32_t a_addr[2], b_addr[2];
#pragma unroll
    for (int mt = 0; mt < 2; mt++) {
        int r = wm * 32 + mt * 16 + (lane & 7) + ((lane >> 3) & 1) * 8;
        int k = (lane >> 4) * 8;
        a_addr[mt] = smem_u32(&As[r][k]);
    }
#pragma unroll
    for (int np = 0; np < 2; np++) {
        int n = wn * 32 + np * 16 + (lane & 7) + (lane >> 4) * 8;
        int k = ((lane >> 3) & 1) * 8;
        b_addr[np] = smem_u32(&Bs[n][k]);
    }

    const int arow = tid >> 2, acol = (tid & 3) * 8;        // A: 2 chunks/thread
    const int brow = tid >> 2, bcol = (tid & 3) * 8;        // B: 1 chunk/thread

    for (int kc = 0; kc < Kp; kc += 32) {
        // stage A: 128 rows x 32 bf16
        {
            uint4 v0 = *(const uint4*)(A + (size_t)(row0 + arow) * Kp + kc + acol);
            uint4 v1 = *(const uint4*)(A + (size_t)(row0 + 64 + arow) * Kp + kc + acol);
            *(uint4*)&As[arow][acol] = v0;
            *(uint4*)&As[64 + arow][acol] = v1;
        }
        // stage B: 64 rows x 32 bf16
        {
            uint4 v = *(const uint4*)(B + (size_t)(col0 + brow) * Kp + kc + bcol);
            *(uint4*)&Bs[brow][bcol] = v;
        }
        __syncthreads();

#pragma unroll
        for (int ks = 0; ks < 2; ks++) {
            uint32_t a[2][4], b[4][2];
#pragma unroll
            for (int mt = 0; mt < 2; mt++) {
                asm volatile("ldmatrix.sync.aligned.m8n8.x4.shared.b16 {%0,%1,%2,%3}, [%4];"
                    : "=r"(a[mt][0]), "=r"(a[mt][1]), "=r"(a[mt][2]), "=r"(a[mt][3])
                    : "r"(a_addr[mt] + ks * 32));
            }
#pragma unroll
            for (int np = 0; np < 2; np++) {
                asm volatile("ldmatrix.sync.aligned.m8n8.x4.shared.b16 {%0,%1,%2,%3}, [%4];"
                    : "=r"(b[np * 2][0]), "=r"(b[np * 2][1]),
                      "=r"(b[np * 2 + 1][0]), "=r"(b[np * 2 + 1][1])
                    : "r"(b_addr[np] + ks * 32));
            }
#pragma unroll
            for (int mt = 0; mt < 2; mt++)
#pragma unroll
                for (int nt = 0; nt < 4; nt++)
                    mma16816(acc[mt][nt], a[mt], b[nt]);
        }
        __syncthreads();
    }

    // epilogue
#pragma unroll
    for (int mt = 0; mt < 2; mt++) {
#pragma unroll
        for (int nt = 0; nt < 4; nt++) {
            int m = row0 + wm * 32 + mt * 16 + (lane >> 2);
            int n = col0 + wn * 32 + nt * 8 + 2 * (lane & 3);
            float c0 = acc[mt][nt][0], c1 = acc[mt][nt][1];
            float c2 = acc[mt][nt][2], c3 = acc[mt][nt][3];
            if (EPI) { c0 = tanhf(c0); c1 = tanhf(c1); c2 = tanhf(c2); c3 = tanhf(c3); }
            *(float2*)&C[(size_t)m * ldc + n] = make_float2(c0, c1);
            *(float2*)&C[(size_t)(m + 8) * ldc + n] = make_float2(c2, c3);
        }
    }
}

// ---------------------------------------------------------------------------
// Energies + masked softmax (register s-blocking, 4 s per thread).
// ---------------------------------------------------------------------------
__global__ void __launch_bounds__(256) attn_energy_softmax(
    const int* __restrict__ lens, const float* __restrict__ v)
{
    __shared__ __align__(16) float sA[4][516];   // WsQ rows (reused as eS)
    __shared__ float sB[256][33];                // WhE chunk [s][32h]
    __shared__ float sV[HH];
    __shared__ float red[8];

    const int b  = blockIdx.y;
    const int t0 = blockIdx.x << 2;
    const int tid = threadIdx.x;
    const int t_local = tid & 3, sg = tid >> 2;

    for (int i = tid; i < 512; i += 256) {
        int row = i >> 7, q = (i & 127) << 2;
        float4 val = *(const float4*)&g_WsQ[((size_t)(b * TB + t0 + row)) * HH + q];
        sA[row][q + 0] = val.x; sA[row][q + 1] = val.y;
        sA[row][q + 2] = val.z; sA[row][q + 3] = val.w;
    }
    for (int i = tid; i < HH; i += 256) sV[i] = v[i];

    float acc0 = 0.f, acc1 = 0.f, acc2 = 0.f, acc3 = 0.f;
    const int srow = sg << 2;

    for (int hc = 0; hc < 16; hc++) {
        __syncthreads();
        for (int i = tid; i < 2048; i += 256) {
            int row = i >> 3, q = (i & 7) << 2;
            float4 val = *(const float4*)
                &g_WhE[((size_t)(b * SB + row)) * HH + (hc << 5) + q];
            sB[row][q + 0] = val.x; sB[row][q + 1] = val.y;
            sB[row][q + 2] = val.z; sB[row][q + 3] = val.w;
        }
        __syncthreads();

        const float* ar = &sA[t_local][hc << 5];
        const float* vr = &sV[hc << 5];
        const float* br = &sB[srow][0];
#pragma unroll 8
        for (int hh = 0; hh < 32; hh++) {
            float a = ar[hh], vv = vr[hh];
            acc0 = fmaf(vv, tanhfast(a + br[hh]),      acc0);
            acc1 = fmaf(vv, tanhfast(a + br[33 + hh]), acc1);
            acc2 = fmaf(vv, tanhfast(a + br[66 + hh]), acc2);
            acc3 = fmaf(vv, tanhfast(a + br[99 + hh]), acc3);
        }
    }

    float* eS = &sA[0][0];
    __syncthreads();
    eS[t_local * 260 + srow + 0] = acc0;
    eS[t_local * 260 + srow + 1] = acc1;
    eS[t_local * 260 + srow + 2] = acc2;
    eS[t_local * 260 + srow + 3] = acc3;
    __syncthreads();

    const int r = tid >> 6, k = tid & 63, s0 = k << 2;
    const int len = lens[b];
    float4 ev = *(float4*)(eS + r * 260 + s0);

    float mloc = -3.0e38f;
    if (s0 + 0 < len) mloc = fmaxf(mloc, ev.x);
    if (s0 + 1 < len) mloc = fmaxf(mloc, ev.y);
    if (s0 + 2 < len) mloc = fmaxf(mloc, ev.z);
    if (s0 + 3 < len) mloc = fmaxf(mloc, ev.w);
#pragma unroll
    for (int o = 16; o; o >>= 1) mloc = fmaxf(mloc, __shfl_xor_sync(~0u, mloc, o));
    if ((tid & 31) == 0) red[tid >> 5] = mloc;
    __syncthreads();
    float m = fmaxf(red[2 * r], red[2 * r + 1]);

    float e0 = (s0 + 0 < len) ? __expf(ev.x - m) : 0.f;
    float e1 = (s0 + 1 < len) ? __expf(ev.y - m) : 0.f;
    float e2 = (s0 + 2 < len) ? __expf(ev.z - m) : 0.f;
    float e3 = (s0 + 3 < len) ? __expf(ev.w - m) : 0.f;
    float sloc = e0 + e1 + e2 + e3;
#pragma unroll
    for (int o = 16; o; o >>= 1) sloc += __shfl_xor_sync(~0u, sloc, o);
    __syncthreads();
    if ((tid & 31) == 0) red[tid >> 5] = sloc;
    __syncthreads();
    float inv = 1.f / (red[2 * r] + red[2 * r + 1]);

    *(float4*)&g_attn[((size_t)(b * TB + t0 + r)) * SB + s0] =
        make_float4(e0 * inv, e1 * inv, e2 * inv, e3 * inv);
}

// ---------------------------------------------------------------------------
// Scalar NN batched GEMM (context): C[b][t][h] = sum_s attn[b][t][s]*enc[b][s][h]
// ---------------------------------------------------------------------------
__device__ __forceinline__ u64 pack2(float lo, float hi) {
    u64 r; asm("mov.b64 %0,{%1,%2};" : "=l"(r) : "f"(lo), "f"(hi)); return r;
}
__device__ __forceinline__ void unpack2(u64 p, float& lo, float& hi) {
    asm("mov.b64 {%0,%1},%2;" : "=f"(lo), "=f"(hi) : "l"(p));
}
__device__ __forceinline__ u64 ffma2(u64 a, u64 b, u64 c) {
    u64 d; asm("fma.rn.f32x2 %0,%1,%2,%3;" : "=l"(d) : "l"(a), "l"(b), "l"(c)); return d;
}

__global__ void __launch_bounds__(256) gemm_nn_kernel(const float* __restrict__ enc)
{
    __shared__ float As[16][68];
    __shared__ float Bs[16][68];
    const int tid = threadIdx.x;
    const int tx = tid & 15, ty = tid >> 4;
    const int b = blockIdx.z;
    const int t0 = blockIdx.y * 64, h0 = blockIdx.x * 64;
    const float* A  = g_attn + (size_t)b * TB * SB;
    const float* Bm = enc    + (size_t)b * SB * HH;
    float* C        = g_ctx  + (size_t)b * TB * HH;

    u64 acc[4][2];
#pragma unroll
    for (int i = 0; i < 4; i++) { acc[i][0] = 0ull; acc[i][1] = 0ull; }

    const int lrowA = tid >> 2;
    const int lk4A  = (tid & 3) << 2;
    const int lrowB = tid >> 4;
    const int lc4B  = (tid & 15) << 2;

    for (int k0 = 0; k0 < SB; k0 += 16) {
        float4 av = *(const float4*)&A[(size_t)(t0 + lrowA) * SB + k0 + lk4A];
        As[lk4A + 0][lrowA] = av.x; As[lk4A + 1][lrowA] = av.y;
        As[lk4A + 2][lrowA] = av.z; As[lk4A + 3][lrowA] = av.w;
        float4 bv = *(const float4*)&Bm[(size_t)(k0 + lrowB) * HH + h0 + lc4B];
        *(float4*)&Bs[lrowB][lc4B] = bv;
        __syncthreads();

#pragma unroll
        for (int kk = 0; kk < 16; kk++) {
            float4 a4 = *(const float4*)&As[kk][ty << 2];
            ulonglong2 b2 = *(const ulonglong2*)&Bs[kk][tx << 2];
            u64 aa;
            aa = pack2(a4.x, a4.x);
            acc[0][0] = ffma2(aa, b2.x, acc[0][0]); acc[0][1] = ffma2(aa, b2.y, acc[0][1]);
            aa = pack2(a4.y, a4.y);
            acc[1][0] = ffma2(aa, b2.x, acc[1][0]); acc[1][1] = ffma2(aa, b2.y, acc[1][1]);
            aa = pack2(a4.z, a4.z);
            acc[2][0] = ffma2(aa, b2.x, acc[2][0]); acc[2][1] = ffma2(aa, b2.y, acc[2][1]);
            aa = pack2(a4.w, a4.w);
            acc[3][0] = ffma2(aa, b2.x, acc[3][0]); acc[3][1] = ffma2(aa, b2.y, acc[3][1]);
        }
        __syncthreads();
    }

#pragma unroll
    for (int i = 0; i < 4; i++) {
        float c0, c1, c2, c3;
        unpack2(acc[i][0], c0, c1);
        unpack2(acc[i][1], c2, c3);
        *(float4*)&C[(size_t)(t0 + (ty << 2) + i) * HH + h0 + (tx << 2)] =
            make_float4(c0, c1, c2, c3);
    }
}

// ---------------------------------------------------------------------------

extern "C" void kernel_launch(void* const* d_in, const int* in_sizes, int n_in,
                              void* d_out, int out_size)
{
    (void)in_sizes; (void)n_in; (void)out_size;
    const float* query = (const float*)d_in[0];
    const float* enc   = (const float*)d_in[1];
    const int*   lens  = (const int*)d_in[2];
    const float* W_s   = (const float*)d_in[3];
    const float* W_h   = (const float*)d_in[4];
    const float* v     = (const float*)d_in[5];
    const float* W_out = (const float*)d_in[6];
    float* out = (float*)d_out;

    float *pWsQ, *pWhE, *pCtx;
    __nv_bfloat16 *pqA, *peA, *pWs3, *pWh3, *pWo3, *pA5;
    cudaGetSymbolAddress((void**)&pWsQ, g_WsQ);
    cudaGetSymbolAddress((void**)&pWhE, g_WhE);
    cudaGetSymbolAddress((void**)&pCtx, g_ctx);
    cudaGetSymbolAddress((void**)&pqA, g_qA);
    cudaGetSymbolAddress((void**)&peA, g_eA);
    cudaGetSymbolAddress((void**)&pWs3, g_Ws3);
    cudaGetSymbolAddress((void**)&pWh3, g_Wh3);
    cudaGetSymbolAddress((void**)&pWo3, g_Wo3);
    cudaGetSymbolAddress((void**)&pA5, g_A5);

    // splits for GEMM operands
    conv3a<<<4096, 256>>>(query, pqA, 512);
    conv3a<<<4096, 256>>>(enc, peA, 512);
    conv3b<<<1024, 256>>>(W_s, pWs3, 512);
    conv3b<<<1024, 256>>>(W_h, pWh3, 512);
    conv3b<<<2048, 256>>>(W_out, pWo3, 1024);

    // 1) WsQ = query @ W_s^T (K'=1536)
    hmma_gemm<0><<<dim3(8, 16), 256>>>(pqA, pWs3, pWsQ, 1536, 512);
    // 2) WhE = enc @ W_h^T
    hmma_gemm<0><<<dim3(8, 16), 256>>>(peA, pWh3, pWhE, 1536, 512);
    // 3) energies + masked softmax
    attn_energy_softmax<<<dim3(64, 8), 256>>>(lens, v);
    // 4) context = attn @ enc (scalar batched NN)
    gemm_nn_kernel<<<dim3(HH / 64, TB / 64, BB), 256>>>(enc);
    // 5) out = tanh([ctx,q] @ W_out^T) (K'=3072)
    conv3cat<<<8192, 256>>>(pCtx, query, pA5);
    hmma_gemm<1><<<dim3(8, 16), 256>>>(pA5, pWo3, out, 3072, 512);
}

// round 4
// speedup vs baseline: 1.6535x; 1.1989x over previous
#include <cuda_runtime.h>
#include <cuda_bf16.h>
#include <cstdint>
#include <math.h>

#define BB 8
#define TB 256
#define SB 256
#define HH 512

// ---------------------------------------------------------------------------
// Static device scratch
// ---------------------------------------------------------------------------
__device__ float g_WsQ[BB * TB * HH];           // 4 MB fp32
__device__ float g_WhE[BB * SB * HH];           // 4 MB fp32
__device__ __nv_bfloat16 g_qA[2048 * 1536];     // query split (A-form)
__device__ __nv_bfloat16 g_eA[2048 * 1536];     // encoder split (A-form, for GEMM2)
__device__ __nv_bfloat16 g_Ws3[512 * 1536];
__device__ __nv_bfloat16 g_Wh3[512 * 1536];
__device__ __nv_bfloat16 g_Wo3[512 * 3072];
__device__ __nv_bfloat16 g_A5[2048 * 3072];     // [ctx|query] split (A-form)
__device__ __nv_bfloat16 g_attnS[BB * TB * 768];  // attn split (A-form), 3 MB
__device__ __nv_bfloat16 g_eT[BB * HH * 768];     // enc^T split (B-form), 6 MB

typedef unsigned long long u64;

__device__ __forceinline__ uint32_t smem_u32(const void* p) {
    uint32_t a;
    asm("{ .reg .u64 t; cvta.to.shared.u64 t, %1; cvt.u32.u64 %0, t; }" : "=r"(a) : "l"(p));
    return a;
}
__device__ __forceinline__ float tanhfast(float x) {
    float y; asm("tanh.approx.f32 %0, %1;" : "=f"(y) : "f"(x)); return y;
}
__device__ __forceinline__ void bfsplit(float x, __nv_bfloat16& h, __nv_bfloat16& l) {
    h = __float2bfloat16(x);
    l = __float2bfloat16(x - __bfloat162float(h));
}

#define CP_ASYNC16(dst, src) \
    asm volatile("cp.async.cg.shared.global [%0], [%1], 16;" :: "r"(dst), "l"(src))
#define CP_COMMIT() asm volatile("cp.async.commit_group;" ::: "memory")
#define CP_WAIT1()  asm volatile("cp.async.wait_group 1;" ::: "memory")
#define CP_WAIT0()  asm volatile("cp.async.wait_group 0;" ::: "memory")

// ---------------------------------------------------------------------------
// Conversion kernels
// ---------------------------------------------------------------------------
// A-style split: out[r*3K+k]=hi, +K=lo, +2K=hi
__global__ void conv3a(const float* __restrict__ X, __nv_bfloat16* __restrict__ O, int K) {
    int idx = blockIdx.x * 256 + threadIdx.x;
    int r = idx / K, k = idx - r * K;
    __nv_bfloat16 h, l; bfsplit(X[idx], h, l);
    size_t base = (size_t)r * 3 * K + k;
    O[base] = h; O[base + K] = l; O[base + 2 * K] = h;
}
// B-style (weights): out[r*3K+k]=hi, +K=hi, +2K=lo
__global__ void conv3b(const float* __restrict__ X, __nv_bfloat16* __restrict__ O, int K) {
    int idx = blockIdx.x * 256 + threadIdx.x;
    int r = idx / K, k = idx - r * K;
    __nv_bfloat16 h, l; bfsplit(X[idx], h, l);
    size_t base = (size_t)r * 3 * K + k;
    O[base] = h; O[base + K] = h; O[base + 2 * K] = l;
}
// query -> A5 columns [512..1024) of the combined K=1024 split
__global__ void convQtoA5(const float* __restrict__ q, __nv_bfloat16* __restrict__ O) {
    int idx = blockIdx.x * 256 + threadIdx.x;   // 2048*512
    int r = idx >> 9, k = idx & 511;
    __nv_bfloat16 h, l; bfsplit(q[idx], h, l);
    size_t base = (size_t)r * 3072 + 512 + k;
    O[base] = h; O[base + 1024] = l; O[base + 2048] = h;
}
// enc (b,s,h) -> eT (b,h, s3) B-style split along s: [s]=hi, [256+s]=hi, [512+s]=lo
__global__ void __launch_bounds__(256) transpose_split_enc(
    const float* __restrict__ enc, __nv_bfloat16* __restrict__ eT)
{
    __shared__ float tile[32][33];
    const int h0 = blockIdx.x * 32, s0 = blockIdx.y * 32, b = blockIdx.z;
    const int tx = threadIdx.x & 31, ty = threadIdx.x >> 5;
    const float* ep = enc + ((size_t)b * SB + s0) * HH + h0;
#pragma unroll
    for (int i = 0; i < 4; i++)
        tile[ty + 8 * i][tx] = ep[(size_t)(ty + 8 * i) * HH + tx];
    __syncthreads();
#pragma unroll
    for (int i = 0; i < 4; i++) {
        int hl = ty + 8 * i, sl = tx;
        __nv_bfloat16 h, l; bfsplit(tile[sl][hl], h, l);
        size_t base = ((size_t)b * HH + h0 + hl) * 768 + s0 + sl;
        eT[base] = h; eT[base + 256] = h; eT[base + 512] = l;
    }
}

// ---------------------------------------------------------------------------
// HMMA GEMM, cp.async double-buffered.
// C[row][col] = sum_k A[row][k]*B[col][k], bf16 K-major both operands.
// 128x64 tile, 8 warps x (32x32), K-chunk 32, 2 stages.
// EPI: 0 = fp32 store, 1 = tanh fp32 store, 2 = hi/lo/hi bf16 split store (A5)
// ---------------------------------------------------------------------------
__device__ __forceinline__ void mma16816(float* c, const uint32_t* a, const uint32_t* b) {
    asm volatile(
        "mma.sync.aligned.m16n8k16.row.col.f32.bf16.bf16.f32 "
        "{%0,%1,%2,%3}, {%4,%5,%6,%7}, {%8,%9}, {%0,%1,%2,%3};"
        : "+f"(c[0]), "+f"(c[1]), "+f"(c[2]), "+f"(c[3])
        : "r"(a[0]), "r"(a[1]), "r"(a[2]), "r"(a[3]), "r"(b[0]), "r"(b[1]));
}

template <int EPI>
__global__ void __launch_bounds__(256) hmma_gemm(
    const __nv_bfloat16* __restrict__ A, const __nv_bfloat16* __restrict__ B,
    void* Cv, int Kp, int ldc, size_t strA, size_t strB, size_t strC)
{
    __shared__ __align__(16) __nv_bfloat16 As[2][128][40];  // 10240 B/stage
    __shared__ __align__(16) __nv_bfloat16 Bs[2][64][40];   //  5120 B/stage

    A += (size_t)blockIdx.z * strA;
    B += (size_t)blockIdx.z * strB;

    const int tid = threadIdx.x, wid = tid >> 5, lane = tid & 31;
    const int row0 = blockIdx.y * 128, col0 = blockIdx.x * 64;
    const int wm = wid & 3, wn = wid >> 2;

    float acc[2][4][4];
#pragma unroll
    for (int mt = 0; mt < 2; mt++)
#pragma unroll
        for (int nt = 0; nt < 4; nt++)
#pragma unroll
            for (int i = 0; i < 4; i++) acc[mt][nt][i] = 0.f;

    // ldmatrix fragment addresses (stage 0; add stage offsets)
    uint32_t a_addr[2], b_addr[2];
#pragma unroll
    for (int mt = 0; mt < 2; mt++) {
        int r = wm * 32 + mt * 16 + (lane & 7) + ((lane >> 3) & 1) * 8;
        int k = (lane >> 4) * 8;
        a_addr[mt] = smem_u32(&As[0][r][k]);
    }
#pragma unroll
    for (int np = 0; np < 2; np++) {
        int n = wn * 32 + np * 16 + (lane & 7) + (lane >> 4) * 8;
        int k = ((lane >> 3) & 1) * 8;
        b_addr[np] = smem_u32(&Bs[0][n][k]);
    }

    // staging addresses
    const int arow = tid >> 2, acol = (tid & 3) * 8;
    uint32_t sA0 = smem_u32(&As[0][arow][acol]);
    uint32_t sA1 = smem_u32(&As[0][64 + arow][acol]);
    uint32_t sB0 = smem_u32(&Bs[0][arow][acol]);   // arow<64 rows used
    const __nv_bfloat16* gA0 = A + (size_t)(row0 + arow) * Kp + acol;
    const __nv_bfloat16* gA1 = A + (size_t)(row0 + 64 + arow) * Kp + acol;
    const __nv_bfloat16* gB0 = B + (size_t)(col0 + arow) * Kp + acol;

#define ISSUE(kc, st) do { \
    uint32_t o = (st) * 10240u; \
    CP_ASYNC16(sA0 + o, gA0 + (kc)); \
    CP_ASYNC16(sA1 + o, gA1 + (kc)); \
    CP_ASYNC16(sB0 + (st) * 5120u, gB0 + (kc)); \
    CP_COMMIT(); \
} while (0)

    const int nch = Kp >> 5;
    ISSUE(0, 0);

    for (int i = 0; i < nch; i++) {
        if (i + 1 < nch) { ISSUE((i + 1) << 5, (i + 1) & 1); CP_WAIT1(); }
        else             { CP_WAIT0(); }
        __syncthreads();

        const uint32_t aoff = (i & 1) * 10240u, boff = (i & 1) * 5120u;
#pragma unroll
        for (int ks = 0; ks < 2; ks++) {
            uint32_t a[2][4], b[4][2];
#pragma unroll
            for (int mt = 0; mt < 2; mt++) {
                asm volatile("ldmatrix.sync.aligned.m8n8.x4.shared.b16 {%0,%1,%2,%3}, [%4];"
                    : "=r"(a[mt][0]), "=r"(a[mt][1]), "=r"(a[mt][2]), "=r"(a[mt][3])
                    : "r"(a_addr[mt] + aoff + ks * 32));
            }
#pragma unroll
            for (int np = 0; np < 2; np++) {
                asm volatile("ldmatrix.sync.aligned.m8n8.x4.shared.b16 {%0,%1,%2,%3}, [%4];"
                    : "=r"(b[np * 2][0]), "=r"(b[np * 2][1]),
                      "=r"(b[np * 2 + 1][0]), "=r"(b[np * 2 + 1][1])
                    : "r"(b_addr[np] + boff + ks * 32));
            }
#pragma unroll
            for (int mt = 0; mt < 2; mt++)
#pragma unroll
                for (int nt = 0; nt < 4; nt++)
                    mma16816(acc[mt][nt], a[mt], b[nt]);
        }
        __syncthreads();
    }
#undef ISSUE

    // epilogue
    if (EPI == 2) {
        __nv_bfloat16* Cb = (__nv_bfloat16*)Cv + (size_t)blockIdx.z * strC;
#pragma unroll
        for (int mt = 0; mt < 2; mt++)
#pragma unroll
            for (int nt = 0; nt < 4; nt++) {
                int m = row0 + wm * 32 + mt * 16 + (lane >> 2);
                int n = col0 + wn * 32 + nt * 8 + 2 * (lane & 3);
#pragma unroll
                for (int rr = 0; rr < 2; rr++) {
                    int mr = m + rr * 8;
                    float v0 = acc[mt][nt][rr * 2], v1 = acc[mt][nt][rr * 2 + 1];
                    __nv_bfloat16 h0, l0, h1, l1;
                    bfsplit(v0, h0, l0); bfsplit(v1, h1, l1);
                    size_t base = (size_t)mr * ldc + n;
                    *(__nv_bfloat162*)&Cb[base]        = __nv_bfloat162(h0, h1);
                    *(__nv_bfloat162*)&Cb[base + 1024] = __nv_bfloat162(l0, l1);
                    *(__nv_bfloat162*)&Cb[base + 2048] = __nv_bfloat162(h0, h1);
                }
            }
    } else {
        float* Cf = (float*)Cv + (size_t)blockIdx.z * strC;
#pragma unroll
        for (int mt = 0; mt < 2; mt++)
#pragma unroll
            for (int nt = 0; nt < 4; nt++) {
                int m = row0 + wm * 32 + mt * 16 + (lane >> 2);
                int n = col0 + wn * 32 + nt * 8 + 2 * (lane & 3);
                float c0 = acc[mt][nt][0], c1 = acc[mt][nt][1];
                float c2 = acc[mt][nt][2], c3 = acc[mt][nt][3];
                if (EPI == 1) { c0 = tanhf(c0); c1 = tanhf(c1); c2 = tanhf(c2); c3 = tanhf(c3); }
                *(float2*)&Cf[(size_t)m * ldc + n] = make_float2(c0, c1);
                *(float2*)&Cf[(size_t)(m + 8) * ldc + n] = make_float2(c2, c3);
            }
    }
}

// ---------------------------------------------------------------------------
// Energies + masked softmax; writes attn directly as bf16 split (A-form, K'=768)
// ---------------------------------------------------------------------------
__global__ void __launch_bounds__(256) attn_energy_softmax(
    const int* __restrict__ lens, const float* __restrict__ v)
{
    __shared__ __align__(16) float sA[4][516];   // WsQ rows (reused as eS)
    __shared__ float sB[256][33];                // WhE chunk [s][32h]
    __shared__ float sV[HH];
    __shared__ float red[8];

    const int b  = blockIdx.y;
    const int t0 = blockIdx.x << 2;
    const int tid = threadIdx.x;
    const int t_local = tid & 3, sg = tid >> 2;

    for (int i = tid; i < 512; i += 256) {
        int row = i >> 7, q = (i & 127) << 2;
        float4 val = *(const float4*)&g_WsQ[((size_t)(b * TB + t0 + row)) * HH + q];
        sA[row][q + 0] = val.x; sA[row][q + 1] = val.y;
        sA[row][q + 2] = val.z; sA[row][q + 3] = val.w;
    }
    for (int i = tid; i < HH; i += 256) sV[i] = v[i];

    float acc0 = 0.f, acc1 = 0.f, acc2 = 0.f, acc3 = 0.f;
    const int srow = sg << 2;

    for (int hc = 0; hc < 16; hc++) {
        __syncthreads();
        for (int i = tid; i < 2048; i += 256) {
            int row = i >> 3, q = (i & 7) << 2;
            float4 val = *(const float4*)
                &g_WhE[((size_t)(b * SB + row)) * HH + (hc << 5) + q];
            sB[row][q + 0] = val.x; sB[row][q + 1] = val.y;
            sB[row][q + 2] = val.z; sB[row][q + 3] = val.w;
        }
        __syncthreads();

        const float* ar = &sA[t_local][hc << 5];
        const float* vr = &sV[hc << 5];
        const float* br = &sB[srow][0];
#pragma unroll 8
        for (int hh = 0; hh < 32; hh++) {
            float a = ar[hh], vv = vr[hh];
            acc0 = fmaf(vv, tanhfast(a + br[hh]),      acc0);
            acc1 = fmaf(vv, tanhfast(a + br[33 + hh]), acc1);
            acc2 = fmaf(vv, tanhfast(a + br[66 + hh]), acc2);
            acc3 = fmaf(vv, tanhfast(a + br[99 + hh]), acc3);
        }
    }

    float* eS = &sA[0][0];
    __syncthreads();
    eS[t_local * 260 + srow + 0] = acc0;
    eS[t_local * 260 + srow + 1] = acc1;
    eS[t_local * 260 + srow + 2] = acc2;
    eS[t_local * 260 + srow + 3] = acc3;
    __syncthreads();

    const int r = tid >> 6, k = tid & 63, s0 = k << 2;
    const int len = lens[b];
    float4 ev = *(float4*)(eS + r * 260 + s0);

    float mloc = -3.0e38f;
    if (s0 + 0 < len) mloc = fmaxf(mloc, ev.x);
    if (s0 + 1 < len) mloc = fmaxf(mloc, ev.y);
    if (s0 + 2 < len) mloc = fmaxf(mloc, ev.z);
    if (s0 + 3 < len) mloc = fmaxf(mloc, ev.w);
#pragma unroll
    for (int o = 16; o; o >>= 1) mloc = fmaxf(mloc, __shfl_xor_sync(~0u, mloc, o));
    if ((tid & 31) == 0) red[tid >> 5] = mloc;
    __syncthreads();
    float m = fmaxf(red[2 * r], red[2 * r + 1]);

    float e0 = (s0 + 0 < len) ? __expf(ev.x - m) : 0.f;
    float e1 = (s0 + 1 < len) ? __expf(ev.y - m) : 0.f;
    float e2 = (s0 + 2 < len) ? __expf(ev.z - m) : 0.f;
    float e3 = (s0 + 3 < len) ? __expf(ev.w - m) : 0.f;
    float sloc = e0 + e1 + e2 + e3;
#pragma unroll
    for (int o = 16; o; o >>= 1) sloc += __shfl_xor_sync(~0u, sloc, o);
    __syncthreads();
    if ((tid & 31) == 0) red[tid >> 5] = sloc;
    __syncthreads();
    float inv = 1.f / (red[2 * r] + red[2 * r + 1]);

    // write attn as bf16 A-form split: [s]=hi, [256+s]=lo, [512+s]=hi
    float w0 = e0 * inv, w1 = e1 * inv, w2 = e2 * inv, w3 = e3 * inv;
    __nv_bfloat16 h0, l0, h1, l1, h2, l2, h3, l3;
    bfsplit(w0, h0, l0); bfsplit(w1, h1, l1);
    bfsplit(w2, h2, l2); bfsplit(w3, h3, l3);
    size_t rb = ((size_t)(b * TB + t0 + r)) * 768;
    __nv_bfloat162 hA(h0, h1), hB(h2, h3), lA(l0, l1), lB(l2, l3);
    *(__nv_bfloat162*)&g_attnS[rb + s0]           = hA;
    *(__nv_bfloat162*)&g_attnS[rb + s0 + 2]       = hB;
    *(__nv_bfloat162*)&g_attnS[rb + 256 + s0]     = lA;
    *(__nv_bfloat162*)&g_attnS[rb + 256 + s0 + 2] = lB;
    *(__nv_bfloat162*)&g_attnS[rb + 512 + s0]     = hA;
    *(__nv_bfloat162*)&g_attnS[rb + 512 + s0 + 2] = hB;
}

// ---------------------------------------------------------------------------

extern "C" void kernel_launch(void* const* d_in, const int* in_sizes, int n_in,
                              void* d_out, int out_size)
{
    (void)in_sizes; (void)n_in; (void)out_size;
    const float* query = (const float*)d_in[0];
    const float* enc   = (const float*)d_in[1];
    const int*   lens  = (const int*)d_in[2];
    const float* W_s   = (const float*)d_in[3];
    const float* W_h   = (const float*)d_in[4];
    const float* v     = (const float*)d_in[5];
    const float* W_out = (const float*)d_in[6];
    float* out = (float*)d_out;

    float *pWsQ, *pWhE;
    __nv_bfloat16 *pqA, *peA, *pWs3, *pWh3, *pWo3, *pA5, *pAttnS, *peT;
    cudaGetSymbolAddress((void**)&pWsQ, g_WsQ);
    cudaGetSymbolAddress((void**)&pWhE, g_WhE);
    cudaGetSymbolAddress((void**)&pqA, g_qA);
    cudaGetSymbolAddress((void**)&peA, g_eA);
    cudaGetSymbolAddress((void**)&pWs3, g_Ws3);
    cudaGetSymbolAddress((void**)&pWh3, g_Wh3);
    cudaGetSymbolAddress((void**)&pWo3, g_Wo3);
    cudaGetSymbolAddress((void**)&pA5, g_A5);
    cudaGetSymbolAddress((void**)&pAttnS, g_attnS);
    cudaGetSymbolAddress((void**)&peT, g_eT);

    // operand conversions
    conv3a<<<4096, 256>>>(query, pqA, 512);
    conv3a<<<4096, 256>>>(enc, peA, 512);
    conv3b<<<1024, 256>>>(W_s, pWs3, 512);
    conv3b<<<1024, 256>>>(W_h, pWh3, 512);
    conv3b<<<2048, 256>>>(W_out, pWo3, 1024);
    convQtoA5<<<4096, 256>>>(query, pA5);
    transpose_split_enc<<<dim3(16, 8, 8), 256>>>(enc, peT);

    // 1) WsQ = query @ W_s^T (K'=1536)
    hmma_gemm<0><<<dim3(8, 16, 1), 256>>>(pqA, pWs3, pWsQ, 1536, 512, 0, 0, 0);
    // 2) WhE = enc @ W_h^T
    hmma_gemm<0><<<dim3(8, 16, 1), 256>>>(peA, pWh3, pWhE, 1536, 512, 0, 0, 0);
    // 3) energies + masked softmax -> attn split bf16
    attn_energy_softmax<<<dim3(64, 8), 256>>>(lens, v);
    // 4) context = attn @ enc  (batched HMMA, K'=768) -> A5 ctx half (split store)
    hmma_gemm<2><<<dim3(8, 2, 8), 256>>>(pAttnS, peT, pA5, 768, 3072,
                                         (size_t)TB * 768, (size_t)HH * 768,
                                         (size_t)TB * 3072);
    // 5) out = tanh([ctx,query] @ W_out^T) (K'=3072)
    hmma_gemm<1><<<dim3(8, 16, 1), 256>>>(pA5, pWo3, out, 3072, 512, 0, 0, 0);
}

// round 5
// speedup vs baseline: 1.8277x; 1.1053x over previous
#include <cuda_runtime.h>
#include <cuda_bf16.h>
#include <cstdint>
#include <math.h>

#define BB 8
#define TB 256
#define SB 256
#define HH 512

// ---------------------------------------------------------------------------
// Static device scratch
// ---------------------------------------------------------------------------
__device__ __nv_bfloat16 g_in3[2 * 2048 * 1536];  // query|enc A-form splits
__device__ __nv_bfloat16 g_W12[2 * 512 * 1536];   // W_s|W_h B-form splits
__device__ __nv_bfloat16 g_Wo3[512 * 3072];       // W_out B-form split
__device__ float g_WW[2 * 2048 * 512];            // WsQ | WhE fp32
__device__ __nv_bfloat16 g_A5[2048 * 3072];       // [ctx|query] split (A-form)
__device__ __nv_bfloat16 g_attnS[BB * TB * 768];  // attn split (A-form)
__device__ __nv_bfloat16 g_eT[BB * HH * 768];     // enc^T split (B-form)

typedef unsigned long long u64;

__device__ __forceinline__ uint32_t smem_u32(const void* p) {
    uint32_t a;
    asm("{ .reg .u64 t; cvta.to.shared.u64 t, %1; cvt.u32.u64 %0, t; }" : "=r"(a) : "l"(p));
    return a;
}
__device__ __forceinline__ float tanhfast(float x) {
    float y; asm("tanh.approx.f32 %0, %1;" : "=f"(y) : "f"(x)); return y;
}
__device__ __forceinline__ void bfsplit(float x, __nv_bfloat16& h, __nv_bfloat16& l) {
    h = __float2bfloat16(x);
    l = __float2bfloat16(x - __bfloat162float(h));
}

#define CP_ASYNC16(dst, src) \
    asm volatile("cp.async.cg.shared.global [%0], [%1], 16;" :: "r"(dst), "l"(src))
#define CP_COMMIT() asm volatile("cp.async.commit_group;" ::: "memory")
#define CP_WAIT2()  asm volatile("cp.async.wait_group 2;" ::: "memory")
#define CP_WAIT1()  asm volatile("cp.async.wait_group 1;" ::: "memory")
#define CP_WAIT0()  asm volatile("cp.async.wait_group 0;" ::: "memory")

// ---------------------------------------------------------------------------
// Fused conversions
// ---------------------------------------------------------------------------
// query+enc -> A-form splits in g_in3; query also -> A5 right half.
__global__ void __launch_bounds__(256) conv_inputs(
    const float* __restrict__ q, const float* __restrict__ enc)
{
    int t = blockIdx.x * 256 + threadIdx.x;          // 524288 threads, 4 elem each
    const int perT = 2048 * 512 / 4;                 // 262144 float4 per tensor
    bool isQ = t < perT;
    int i4 = isQ ? t : t - perT;
    int r = i4 >> 7, k = (i4 & 127) << 2;
    const float* src = isQ ? q : enc;
    float4 x = *(const float4*)&src[(size_t)r * 512 + k];
    __nv_bfloat16 h0, l0, h1, l1, h2, l2, h3, l3;
    bfsplit(x.x, h0, l0); bfsplit(x.y, h1, l1);
    bfsplit(x.z, h2, l2); bfsplit(x.w, h3, l3);
    __nv_bfloat162 hA(h0, h1), hB(h2, h3), lA(l0, l1), lB(l2, l3);

    size_t base = (isQ ? 0 : (size_t)2048 * 1536) + (size_t)r * 1536 + k;
    *(__nv_bfloat162*)&g_in3[base]            = hA;
    *(__nv_bfloat162*)&g_in3[base + 2]        = hB;
    *(__nv_bfloat162*)&g_in3[base + 512]      = lA;
    *(__nv_bfloat162*)&g_in3[base + 512 + 2]  = lB;
    *(__nv_bfloat162*)&g_in3[base + 1024]     = hA;
    *(__nv_bfloat162*)&g_in3[base + 1024 + 2] = hB;

    if (isQ) {
        size_t b5 = (size_t)r * 3072 + 512 + k;
        *(__nv_bfloat162*)&g_A5[b5]            = hA;
        *(__nv_bfloat162*)&g_A5[b5 + 2]        = hB;
        *(__nv_bfloat162*)&g_A5[b5 + 1024]     = lA;
        *(__nv_bfloat162*)&g_A5[b5 + 1024 + 2] = lB;
        *(__nv_bfloat162*)&g_A5[b5 + 2048]     = hA;
        *(__nv_bfloat162*)&g_A5[b5 + 2048 + 2] = hB;
    }
}

// W_s, W_h, W_out -> B-form splits
__global__ void __launch_bounds__(256) conv_weights(
    const float* __restrict__ Ws, const float* __restrict__ Wh,
    const float* __restrict__ Wo)
{
    int t = blockIdx.x * 256 + threadIdx.x;     // 262144 threads
    const float* src; __nv_bfloat16* dst; int K, i4;
    if (t < 65536)        { src = Ws; dst = g_W12;                K = 512;  i4 = t; }
    else if (t < 131072)  { src = Wh; dst = g_W12 + 512 * 1536;   K = 512;  i4 = t - 65536; }
    else                  { src = Wo; dst = g_Wo3;                K = 1024; i4 = t - 131072; }
    int kq = K >> 2;
    int r = i4 / kq, k = (i4 - r * kq) << 2;
    float4 x = *(const float4*)&src[(size_t)r * K + k];
    __nv_bfloat16 h0, l0, h1, l1, h2, l2, h3, l3;
    bfsplit(x.x, h0, l0); bfsplit(x.y, h1, l1);
    bfsplit(x.z, h2, l2); bfsplit(x.w, h3, l3);
    __nv_bfloat162 hA(h0, h1), hB(h2, h3), lA(l0, l1), lB(l2, l3);
    size_t base = (size_t)r * 3 * K + k;
    *(__nv_bfloat162*)&dst[base]             = hA;
    *(__nv_bfloat162*)&dst[base + 2]         = hB;
    *(__nv_bfloat162*)&dst[base + K]         = hA;
    *(__nv_bfloat162*)&dst[base + K + 2]     = hB;
    *(__nv_bfloat162*)&dst[base + 2 * K]     = lA;
    *(__nv_bfloat162*)&dst[base + 2 * K + 2] = lB;
}

// enc (b,s,h) -> eT (b,h,s3) B-form split along s
__global__ void __launch_bounds__(256) transpose_split_enc(
    const float* __restrict__ enc, __nv_bfloat16* __restrict__ eT)
{
    __shared__ float tile[32][33];
    const int h0 = blockIdx.x * 32, s0 = blockIdx.y * 32, b = blockIdx.z;
    const int tx = threadIdx.x & 31, ty = threadIdx.x >> 5;
    const float* ep = enc + ((size_t)b * SB + s0) * HH + h0;
#pragma unroll
    for (int i = 0; i < 4; i++)
        tile[ty + 8 * i][tx] = ep[(size_t)(ty + 8 * i) * HH + tx];
    __syncthreads();
#pragma unroll
    for (int i = 0; i < 4; i++) {
        int hl = ty + 8 * i, sl = tx;
        __nv_bfloat16 h, l; bfsplit(tile[sl][hl], h, l);
        size_t base = ((size_t)b * HH + h0 + hl) * 768 + s0 + sl;
        eT[base] = h; eT[base + 256] = h; eT[base + 512] = l;
    }
}

// ---------------------------------------------------------------------------
// HMMA GEMM, 3-stage cp.async ring. 128x64 tile, 8 warps x (32x32), K-chunk 32.
// EPI: 0 = fp32, 1 = tanh fp32, 2 = hi/lo/hi bf16 split store (A5 ctx half)
// ---------------------------------------------------------------------------
__device__ __forceinline__ void mma16816(float* c, const uint32_t* a, const uint32_t* b) {
    asm volatile(
        "mma.sync.aligned.m16n8k16.row.col.f32.bf16.bf16.f32 "
        "{%0,%1,%2,%3}, {%4,%5,%6,%7}, {%8,%9}, {%0,%1,%2,%3};"
        : "+f"(c[0]), "+f"(c[1]), "+f"(c[2]), "+f"(c[3])
        : "r"(a[0]), "r"(a[1]), "r"(a[2]), "r"(a[3]), "r"(b[0]), "r"(b[1]));
}

template <int EPI>
__global__ void __launch_bounds__(256) hmma_gemm(
    const __nv_bfloat16* __restrict__ A, const __nv_bfloat16* __restrict__ B,
    void* Cv, int Kp, int ldc, size_t strA, size_t strB, size_t strC)
{
    __shared__ __align__(16) __nv_bfloat16 As[3][128][40];  // 10240 B/stage
    __shared__ __align__(16) __nv_bfloat16 Bs[3][64][40];   //  5120 B/stage

    A += (size_t)blockIdx.z * strA;
    B += (size_t)blockIdx.z * strB;

    const int tid = threadIdx.x, wid = tid >> 5, lane = tid & 31;
    const int row0 = blockIdx.y * 128, col0 = blockIdx.x * 64;
    const int wm = wid & 3, wn = wid >> 2;

    float acc[2][4][4];
#pragma unroll
    for (int mt = 0; mt < 2; mt++)
#pragma unroll
        for (int nt = 0; nt < 4; nt++)
#pragma unroll
            for (int i = 0; i < 4; i++) acc[mt][nt][i] = 0.f;

    uint32_t a_addr[2], b_addr[2];
#pragma unroll
    for (int mt = 0; mt < 2; mt++) {
        int r = wm * 32 + mt * 16 + (lane & 7) + ((lane >> 3) & 1) * 8;
        int k = (lane >> 4) * 8;
        a_addr[mt] = smem_u32(&As[0][r][k]);
    }
#pragma unroll
    for (int np = 0; np < 2; np++) {
        int n = wn * 32 + np * 16 + (lane & 7) + (lane >> 4) * 8;
        int k = ((lane >> 3) & 1) * 8;
        b_addr[np] = smem_u32(&Bs[0][n][k]);
    }

    const int arow = tid >> 2, acol = (tid & 3) * 8;
    uint32_t sA0 = smem_u32(&As[0][arow][acol]);
    uint32_t sA1 = smem_u32(&As[0][64 + arow][acol]);
    uint32_t sB0 = smem_u32(&Bs[0][arow][acol]);
    const __nv_bfloat16* gA0 = A + (size_t)(row0 + arow) * Kp + acol;
    const __nv_bfloat16* gA1 = A + (size_t)(row0 + 64 + arow) * Kp + acol;
    const __nv_bfloat16* gB0 = B + (size_t)(col0 + arow) * Kp + acol;

#define ISSUE(kc, st) do { \
    uint32_t o = (uint32_t)(st) * 10240u; \
    CP_ASYNC16(sA0 + o, gA0 + (kc)); \
    CP_ASYNC16(sA1 + o, gA1 + (kc)); \
    CP_ASYNC16(sB0 + (uint32_t)(st) * 5120u, gB0 + (kc)); \
    CP_COMMIT(); \
} while (0)

    const int nch = Kp >> 5;
    ISSUE(0, 0);
    if (nch > 1) ISSUE(32, 1);

    int stage = 0;
    for (int i = 0; i < nch; i++) {
        if (i + 2 < nch) {
            int s2 = stage + 2; if (s2 >= 3) s2 -= 3;
            ISSUE((i + 2) << 5, s2);
            CP_WAIT2();
        } else if (i + 1 < nch) {
            CP_WAIT1();
        } else {
            CP_WAIT0();
        }
        __syncthreads();

        const uint32_t aoff = (uint32_t)stage * 10240u, boff = (uint32_t)stage * 5120u;
#pragma unroll
        for (int ks = 0; ks < 2; ks++) {
            uint32_t a[2][4], b[4][2];
#pragma unroll
            for (int mt = 0; mt < 2; mt++) {
                asm volatile("ldmatrix.sync.aligned.m8n8.x4.shared.b16 {%0,%1,%2,%3}, [%4];"
                    : "=r"(a[mt][0]), "=r"(a[mt][1]), "=r"(a[mt][2]), "=r"(a[mt][3])
                    : "r"(a_addr[mt] + aoff + ks * 32));
            }
#pragma unroll
            for (int np = 0; np < 2; np++) {
                asm volatile("ldmatrix.sync.aligned.m8n8.x4.shared.b16 {%0,%1,%2,%3}, [%4];"
                    : "=r"(b[np * 2][0]), "=r"(b[np * 2][1]),
                      "=r"(b[np * 2 + 1][0]), "=r"(b[np * 2 + 1][1])
                    : "r"(b_addr[np] + boff + ks * 32));
            }
#pragma unroll
            for (int mt = 0; mt < 2; mt++)
#pragma unroll
                for (int nt = 0; nt < 4; nt++)
                    mma16816(acc[mt][nt], a[mt], b[nt]);
        }
        __syncthreads();
        if (++stage == 3) stage = 0;
    }
#undef ISSUE

    if (EPI == 2) {
        __nv_bfloat16* Cb = (__nv_bfloat16*)Cv + (size_t)blockIdx.z * strC;
#pragma unroll
        for (int mt = 0; mt < 2; mt++)
#pragma unroll
            for (int nt = 0; nt < 4; nt++) {
                int m = row0 + wm * 32 + mt * 16 + (lane >> 2);
                int n = col0 + wn * 32 + nt * 8 + 2 * (lane & 3);
#pragma unroll
                for (int rr = 0; rr < 2; rr++) {
                    int mr = m + rr * 8;
                    float v0 = acc[mt][nt][rr * 2], v1 = acc[mt][nt][rr * 2 + 1];
                    __nv_bfloat16 h0, l0, h1, l1;
                    bfsplit(v0, h0, l0); bfsplit(v1, h1, l1);
                    size_t base = (size_t)mr * ldc + n;
                    *(__nv_bfloat162*)&Cb[base]        = __nv_bfloat162(h0, h1);
                    *(__nv_bfloat162*)&Cb[base + 1024] = __nv_bfloat162(l0, l1);
                    *(__nv_bfloat162*)&Cb[base + 2048] = __nv_bfloat162(h0, h1);
                }
            }
    } else {
        float* Cf = (float*)Cv + (size_t)blockIdx.z * strC;
#pragma unroll
        for (int mt = 0; mt < 2; mt++)
#pragma unroll
            for (int nt = 0; nt < 4; nt++) {
                int m = row0 + wm * 32 + mt * 16 + (lane >> 2);
                int n = col0 + wn * 32 + nt * 8 + 2 * (lane & 3);
                float c0 = acc[mt][nt][0], c1 = acc[mt][nt][1];
                float c2 = acc[mt][nt][2], c3 = acc[mt][nt][3];
                if (EPI == 1) { c0 = tanhf(c0); c1 = tanhf(c1); c2 = tanhf(c2); c3 = tanhf(c3); }
                *(float2*)&Cf[(size_t)m * ldc + n] = make_float2(c0, c1);
                *(float2*)&Cf[(size_t)(m + 8) * ldc + n] = make_float2(c2, c3);
            }
    }
}

// ---------------------------------------------------------------------------
// Energies + masked softmax; writes attn directly as bf16 split (A-form)
// WsQ = g_WW[0..2048*512), WhE = g_WW[2048*512..)
// ---------------------------------------------------------------------------
__global__ void __launch_bounds__(256) attn_energy_softmax(
    const int* __restrict__ lens, const float* __restrict__ v)
{
    __shared__ __align__(16) float sA[4][516];
    __shared__ float sB[256][33];
    __shared__ float sV[HH];
    __shared__ float red[8];

    const int b  = blockIdx.y;
    const int t0 = blockIdx.x << 2;
    const int tid = threadIdx.x;
    const int t_local = tid & 3, sg = tid >> 2;
    const float* WsQ = g_WW;
    const float* WhE = g_WW + (size_t)2048 * 512;

    for (int i = tid; i < 512; i += 256) {
        int row = i >> 7, q = (i & 127) << 2;
        float4 val = *(const float4*)&WsQ[((size_t)(b * TB + t0 + row)) * HH + q];
        sA[row][q + 0] = val.x; sA[row][q + 1] = val.y;
        sA[row][q + 2] = val.z; sA[row][q + 3] = val.w;
    }
    for (int i = tid; i < HH; i += 256) sV[i] = v[i];

    float acc0 = 0.f, acc1 = 0.f, acc2 = 0.f, acc3 = 0.f;
    const int srow = sg << 2;

    for (int hc = 0; hc < 16; hc++) {
        __syncthreads();
        for (int i = tid; i < 2048; i += 256) {
            int row = i >> 3, q = (i & 7) << 2;
            float4 val = *(const float4*)
                &WhE[((size_t)(b * SB + row)) * HH + (hc << 5) + q];
            sB[row][q + 0] = val.x; sB[row][q + 1] = val.y;
            sB[row][q + 2] = val.z; sB[row][q + 3] = val.w;
        }
        __syncthreads();

        const float* ar = &sA[t_local][hc << 5];
        const float* vr = &sV[hc << 5];
        const float* br = &sB[srow][0];
#pragma unroll 8
        for (int hh = 0; hh < 32; hh++) {
            float a = ar[hh], vv = vr[hh];
            acc0 = fmaf(vv, tanhfast(a + br[hh]),      acc0);
            acc1 = fmaf(vv, tanhfast(a + br[33 + hh]), acc1);
            acc2 = fmaf(vv, tanhfast(a + br[66 + hh]), acc2);
            acc3 = fmaf(vv, tanhfast(a + br[99 + hh]), acc3);
        }
    }

    float* eS = &sA[0][0];
    __syncthreads();
    eS[t_local * 260 + srow + 0] = acc0;
    eS[t_local * 260 + srow + 1] = acc1;
    eS[t_local * 260 + srow + 2] = acc2;
    eS[t_local * 260 + srow + 3] = acc3;
    __syncthreads();

    const int r = tid >> 6, k = tid & 63, s0 = k << 2;
    const int len = lens[b];
    float4 ev = *(float4*)(eS + r * 260 + s0);

    float mloc = -3.0e38f;
    if (s0 + 0 < len) mloc = fmaxf(mloc, ev.x);
    if (s0 + 1 < len) mloc = fmaxf(mloc, ev.y);
    if (s0 + 2 < len) mloc = fmaxf(mloc, ev.z);
    if (s0 + 3 < len) mloc = fmaxf(mloc, ev.w);
#pragma unroll
    for (int o = 16; o; o >>= 1) mloc = fmaxf(mloc, __shfl_xor_sync(~0u, mloc, o));
    if ((tid & 31) == 0) red[tid >> 5] = mloc;
    __syncthreads();
    float m = fmaxf(red[2 * r], red[2 * r + 1]);

    float e0 = (s0 + 0 < len) ? __expf(ev.x - m) : 0.f;
    float e1 = (s0 + 1 < len) ? __expf(ev.y - m) : 0.f;
    float e2 = (s0 + 2 < len) ? __expf(ev.z - m) : 0.f;
    float e3 = (s0 + 3 < len) ? __expf(ev.w - m) : 0.f;
    float sloc = e0 + e1 + e2 + e3;
#pragma unroll
    for (int o = 16; o; o >>= 1) sloc += __shfl_xor_sync(~0u, sloc, o);
    __syncthreads();
    if ((tid & 31) == 0) red[tid >> 5] = sloc;
    __syncthreads();
    float inv = 1.f / (red[2 * r] + red[2 * r + 1]);

    float w0 = e0 * inv, w1 = e1 * inv, w2 = e2 * inv, w3 = e3 * inv;
    __nv_bfloat16 h0, l0, h1, l1, h2, l2, h3, l3;
    bfsplit(w0, h0, l0); bfsplit(w1, h1, l1);
    bfsplit(w2, h2, l2); bfsplit(w3, h3, l3);
    size_t rb = ((size_t)(b * TB + t0 + r)) * 768;
    __nv_bfloat162 hA(h0, h1), hB(h2, h3), lA(l0, l1), lB(l2, l3);
    *(__nv_bfloat162*)&g_attnS[rb + s0]           = hA;
    *(__nv_bfloat162*)&g_attnS[rb + s0 + 2]       = hB;
    *(__nv_bfloat162*)&g_attnS[rb + 256 + s0]     = lA;
    *(__nv_bfloat162*)&g_attnS[rb + 256 + s0 + 2] = lB;
    *(__nv_bfloat162*)&g_attnS[rb + 512 + s0]     = hA;
    *(__nv_bfloat162*)&g_attnS[rb + 512 + s0 + 2] = hB;
}

// ---------------------------------------------------------------------------

extern "C" void kernel_launch(void* const* d_in, const int* in_sizes, int n_in,
                              void* d_out, int out_size)
{
    (void)in_sizes; (void)n_in; (void)out_size;
    const float* query = (const float*)d_in[0];
    const float* enc   = (const float*)d_in[1];
    const int*   lens  = (const int*)d_in[2];
    const float* W_s   = (const float*)d_in[3];
    const float* W_h   = (const float*)d_in[4];
    const float* v     = (const float*)d_in[5];
    const float* W_out = (const float*)d_in[6];
    float* out = (float*)d_out;

    __nv_bfloat16 *pin3, *pW12, *pWo3, *pA5, *pAttnS, *peT;
    float* pWW;
    cudaGetSymbolAddress((void**)&pin3, g_in3);
    cudaGetSymbolAddress((void**)&pW12, g_W12);
    cudaGetSymbolAddress((void**)&pWo3, g_Wo3);
    cudaGetSymbolAddress((void**)&pWW, g_WW);
    cudaGetSymbolAddress((void**)&pA5, g_A5);
    cudaGetSymbolAddress((void**)&pAttnS, g_attnS);
    cudaGetSymbolAddress((void**)&peT, g_eT);

    // conversions (3 kernels)
    conv_inputs<<<2048, 256>>>(query, enc);
    conv_weights<<<1024, 256>>>(W_s, W_h, W_out);
    transpose_split_enc<<<dim3(16, 8, 8), 256>>>(enc, peT);

    // 1+2) WsQ / WhE batched (z=2), K'=1536
    hmma_gemm<0><<<dim3(8, 16, 2), 256>>>(pin3, pW12, pWW, 1536, 512,
                                          (size_t)2048 * 1536, (size_t)512 * 1536,
                                          (size_t)2048 * 512);
    // 3) energies + masked softmax -> attn split bf16
    attn_energy_softmax<<<dim3(64, 8), 256>>>(lens, v);
    // 4) context = attn @ enc (batched, K'=768) -> A5 ctx half (split store)
    hmma_gemm<2><<<dim3(8, 2, 8), 256>>>(pAttnS, peT, pA5, 768, 3072,
                                         (size_t)TB * 768, (size_t)HH * 768,
                                         (size_t)TB * 3072);
    // 5) out = tanh([ctx,query] @ W_out^T), K'=3072
    hmma_gemm<1><<<dim3(8, 16, 1), 256>>>(pA5, pWo3, out, 3072, 512, 0, 0, 0);
}

// round 6
// speedup vs baseline: 1.8839x; 1.0308x over previous
#include <cuda_runtime.h>
#include <cuda_bf16.h>
#include <cstdint>
#include <math.h>

#define BB 8
#define TB 256
#define SB 256
#define HH 512

// ---------------------------------------------------------------------------
// Static device scratch
// ---------------------------------------------------------------------------
__device__ __nv_bfloat16 g_in3[2 * 2048 * 1536];  // query|enc A-form splits
__device__ __nv_bfloat16 g_W12[2 * 512 * 1536];   // W_s|W_h B-form splits
__device__ __nv_bfloat16 g_Wo3[512 * 3072];       // W_out B-form split
__device__ float g_WW[2 * 2048 * 512];            // WsQ | WhE fp32
__device__ __nv_bfloat16 g_A5[2048 * 3072];       // [ctx|query] split (A-form)
__device__ __nv_bfloat16 g_attnS[BB * TB * 768];  // attn split (A-form)
__device__ __nv_bfloat16 g_eT[BB * HH * 768];     // enc^T split (B-form)
__device__ float g_P5[2 * 2048 * 512];            // split-K partials for out GEMM

typedef unsigned long long u64;

__device__ __forceinline__ uint32_t smem_u32(const void* p) {
    uint32_t a;
    asm("{ .reg .u64 t; cvta.to.shared.u64 t, %1; cvt.u32.u64 %0, t; }" : "=r"(a) : "l"(p));
    return a;
}
__device__ __forceinline__ float tanhfast(float x) {
    float y; asm("tanh.approx.f32 %0, %1;" : "=f"(y) : "f"(x)); return y;
}
__device__ __forceinline__ void bfsplit(float x, __nv_bfloat16& h, __nv_bfloat16& l) {
    h = __float2bfloat16(x);
    l = __float2bfloat16(x - __bfloat162float(h));
}

#define CP_ASYNC16(dst, src) \
    asm volatile("cp.async.cg.shared.global [%0], [%1], 16;" :: "r"(dst), "l"(src))
#define CP_COMMIT() asm volatile("cp.async.commit_group;" ::: "memory")
#define CP_WAIT2()  asm volatile("cp.async.wait_group 2;" ::: "memory")
#define CP_WAIT1()  asm volatile("cp.async.wait_group 1;" ::: "memory")
#define CP_WAIT0()  asm volatile("cp.async.wait_group 0;" ::: "memory")

// ---------------------------------------------------------------------------
// Fused conversions
// ---------------------------------------------------------------------------
__global__ void __launch_bounds__(256) conv_inputs(
    const float* __restrict__ q, const float* __restrict__ enc)
{
    int t = blockIdx.x * 256 + threadIdx.x;
    const int perT = 2048 * 512 / 4;
    bool isQ = t < perT;
    int i4 = isQ ? t : t - perT;
    int r = i4 >> 7, k = (i4 & 127) << 2;
    const float* src = isQ ? q : enc;
    float4 x = *(const float4*)&src[(size_t)r * 512 + k];
    __nv_bfloat16 h0, l0, h1, l1, h2, l2, h3, l3;
    bfsplit(x.x, h0, l0); bfsplit(x.y, h1, l1);
    bfsplit(x.z, h2, l2); bfsplit(x.w, h3, l3);
    __nv_bfloat162 hA(h0, h1), hB(h2, h3), lA(l0, l1), lB(l2, l3);

    size_t base = (isQ ? 0 : (size_t)2048 * 1536) + (size_t)r * 1536 + k;
    *(__nv_bfloat162*)&g_in3[base]            = hA;
    *(__nv_bfloat162*)&g_in3[base + 2]        = hB;
    *(__nv_bfloat162*)&g_in3[base + 512]      = lA;
    *(__nv_bfloat162*)&g_in3[base + 512 + 2]  = lB;
    *(__nv_bfloat162*)&g_in3[base + 1024]     = hA;
    *(__nv_bfloat162*)&g_in3[base + 1024 + 2] = hB;

    if (isQ) {
        size_t b5 = (size_t)r * 3072 + 512 + k;
        *(__nv_bfloat162*)&g_A5[b5]            = hA;
        *(__nv_bfloat162*)&g_A5[b5 + 2]        = hB;
        *(__nv_bfloat162*)&g_A5[b5 + 1024]     = lA;
        *(__nv_bfloat162*)&g_A5[b5 + 1024 + 2] = lB;
        *(__nv_bfloat162*)&g_A5[b5 + 2048]     = hA;
        *(__nv_bfloat162*)&g_A5[b5 + 2048 + 2] = hB;
    }
}

__global__ void __launch_bounds__(256) conv_weights(
    const float* __restrict__ Ws, const float* __restrict__ Wh,
    const float* __restrict__ Wo)
{
    int t = blockIdx.x * 256 + threadIdx.x;
    const float* src; __nv_bfloat16* dst; int K, i4;
    if (t < 65536)        { src = Ws; dst = g_W12;                K = 512;  i4 = t; }
    else if (t < 131072)  { src = Wh; dst = g_W12 + 512 * 1536;   K = 512;  i4 = t - 65536; }
    else                  { src = Wo; dst = g_Wo3;                K = 1024; i4 = t - 131072; }
    int kq = K >> 2;
    int r = i4 / kq, k = (i4 - r * kq) << 2;
    float4 x = *(const float4*)&src[(size_t)r * K + k];
    __nv_bfloat16 h0, l0, h1, l1, h2, l2, h3, l3;
    bfsplit(x.x, h0, l0); bfsplit(x.y, h1, l1);
    bfsplit(x.z, h2, l2); bfsplit(x.w, h3, l3);
    __nv_bfloat162 hA(h0, h1), hB(h2, h3), lA(l0, l1), lB(l2, l3);
    size_t base = (size_t)r * 3 * K + k;
    *(__nv_bfloat162*)&dst[base]             = hA;
    *(__nv_bfloat162*)&dst[base + 2]         = hB;
    *(__nv_bfloat162*)&dst[base + K]         = hA;
    *(__nv_bfloat162*)&dst[base + K + 2]     = hB;
    *(__nv_bfloat162*)&dst[base + 2 * K]     = lA;
    *(__nv_bfloat162*)&dst[base + 2 * K + 2] = lB;
}

__global__ void __launch_bounds__(256) transpose_split_enc(
    const float* __restrict__ enc, __nv_bfloat16* __restrict__ eT)
{
    __shared__ float tile[32][33];
    const int h0 = blockIdx.x * 32, s0 = blockIdx.y * 32, b = blockIdx.z;
    const int tx = threadIdx.x & 31, ty = threadIdx.x >> 5;
    const float* ep = enc + ((size_t)b * SB + s0) * HH + h0;
#pragma unroll
    for (int i = 0; i < 4; i++)
        tile[ty + 8 * i][tx] = ep[(size_t)(ty + 8 * i) * HH + tx];
    __syncthreads();
#pragma unroll
    for (int i = 0; i < 4; i++) {
        int hl = ty + 8 * i, sl = tx;
        __nv_bfloat16 h, l; bfsplit(tile[sl][hl], h, l);
        size_t base = ((size_t)b * HH + h0 + hl) * 768 + s0 + sl;
        eT[base] = h; eT[base + 256] = h; eT[base + 512] = l;
    }
}

// ---------------------------------------------------------------------------
// HMMA GEMM, 3-stage cp.async ring.
// Tile 128 x NT (NT=64 or 128), 8 warps (wm 0..3, wn 0..1), K-chunk 32.
// K_len = summed K; Kld = row stride of A and B (K_len<=Kld enables split-K).
// EPI: 0 = fp32, 1 = tanh fp32, 2 = hi/lo/hi bf16 split store (A5 ctx half)
// ---------------------------------------------------------------------------
__device__ __forceinline__ void mma16816(float* c, const uint32_t* a, const uint32_t* b) {
    asm volatile(
        "mma.sync.aligned.m16n8k16.row.col.f32.bf16.bf16.f32 "
        "{%0,%1,%2,%3}, {%4,%5,%6,%7}, {%8,%9}, {%0,%1,%2,%3};"
        : "+f"(c[0]), "+f"(c[1]), "+f"(c[2]), "+f"(c[3])
        : "r"(a[0]), "r"(a[1]), "r"(a[2]), "r"(a[3]), "r"(b[0]), "r"(b[1]));
}

template <int EPI, int NT>
__global__ void __launch_bounds__(256) hmma_gemm(
    const __nv_bfloat16* __restrict__ A, const __nv_bfloat16* __restrict__ B,
    void* Cv, int K_len, int Kld, int ldc, size_t strA, size_t strB, size_t strC)
{
    constexpr int NPG = NT / 32;   // ldmatrix.x4 b-groups per warp (16 rows each)
    constexpr int NTT = NT / 16;   // 8-col n-subtiles per warp
    constexpr uint32_t ASZ = 128 * 40 * 2;
    constexpr uint32_t BSZ = NT * 40 * 2;

    __shared__ __align__(16) __nv_bfloat16 As[3][128][40];
    __shared__ __align__(16) __nv_bfloat16 Bs[3][NT][40];

    A += (size_t)blockIdx.z * strA;
    B += (size_t)blockIdx.z * strB;

    const int tid = threadIdx.x, wid = tid >> 5, lane = tid & 31;
    const int row0 = blockIdx.y * 128, col0 = blockIdx.x * NT;
    const int wm = wid & 3, wn = wid >> 2;

    float acc[2][NTT][4];
#pragma unroll
    for (int mt = 0; mt < 2; mt++)
#pragma unroll
        for (int nt = 0; nt < NTT; nt++)
#pragma unroll
            for (int i = 0; i < 4; i++) acc[mt][nt][i] = 0.f;

    uint32_t a_addr[2], b_addr[NPG];
#pragma unroll
    for (int mt = 0; mt < 2; mt++) {
        int r = wm * 32 + mt * 16 + (lane & 7) + ((lane >> 3) & 1) * 8;
        int k = (lane >> 4) * 8;
        a_addr[mt] = smem_u32(&As[0][r][k]);
    }
#pragma unroll
    for (int np = 0; np < NPG; np++) {
        int n = wn * (NT / 2) + np * 16 + (lane & 7) + (lane >> 4) * 8;
        int k = ((lane >> 3) & 1) * 8;
        b_addr[np] = smem_u32(&Bs[0][n][k]);
    }

    const int arow = tid >> 2, acol = (tid & 3) * 8;
    uint32_t sA0 = smem_u32(&As[0][arow][acol]);
    uint32_t sA1 = smem_u32(&As[0][64 + arow][acol]);
    uint32_t sB0 = smem_u32(&Bs[0][arow][acol]);
    uint32_t sB1 = (NT == 128) ? smem_u32(&Bs[0][(NT == 128 ? 64 : 0) + arow][acol]) : 0;
    const __nv_bfloat16* gA0 = A + (size_t)(row0 + arow) * Kld + acol;
    const __nv_bfloat16* gA1 = A + (size_t)(row0 + 64 + arow) * Kld + acol;
    const __nv_bfloat16* gB0 = B + (size_t)(col0 + arow) * Kld + acol;
    const __nv_bfloat16* gB1 = (NT == 128)
        ? B + (size_t)(col0 + 64 + arow) * Kld + acol : gB0;

#define ISSUE(kc, st) do { \
    uint32_t ao = (uint32_t)(st) * ASZ, bo = (uint32_t)(st) * BSZ; \
    CP_ASYNC16(sA0 + ao, gA0 + (kc)); \
    CP_ASYNC16(sA1 + ao, gA1 + (kc)); \
    CP_ASYNC16(sB0 + bo, gB0 + (kc)); \
    if (NT == 128) CP_ASYNC16(sB1 + bo, gB1 + (kc)); \
    CP_COMMIT(); \
} while (0)

    const int nch = K_len >> 5;
    ISSUE(0, 0);
    if (nch > 1) ISSUE(32, 1);

    int stage = 0;
    for (int i = 0; i < nch; i++) {
        if (i + 2 < nch) {
            int s2 = stage + 2; if (s2 >= 3) s2 -= 3;
            ISSUE((i + 2) << 5, s2);
            CP_WAIT2();
        } else if (i + 1 < nch) {
            CP_WAIT1();
        } else {
            CP_WAIT0();
        }
        __syncthreads();

        const uint32_t aoff = (uint32_t)stage * ASZ, boff = (uint32_t)stage * BSZ;
#pragma unroll
        for (int ks = 0; ks < 2; ks++) {
            uint32_t a[2][4], b[NTT][2];
#pragma unroll
            for (int mt = 0; mt < 2; mt++) {
                asm volatile("ldmatrix.sync.aligned.m8n8.x4.shared.b16 {%0,%1,%2,%3}, [%4];"
                    : "=r"(a[mt][0]), "=r"(a[mt][1]), "=r"(a[mt][2]), "=r"(a[mt][3])
                    : "r"(a_addr[mt] + aoff + ks * 32));
            }
#pragma unroll
            for (int np = 0; np < NPG; np++) {
                asm volatile("ldmatrix.sync.aligned.m8n8.x4.shared.b16 {%0,%1,%2,%3}, [%4];"
                    : "=r"(b[np * 2][0]), "=r"(b[np * 2][1]),
                      "=r"(b[np * 2 + 1][0]), "=r"(b[np * 2 + 1][1])
                    : "r"(b_addr[np] + boff + ks * 32));
            }
#pragma unroll
            for (int mt = 0; mt < 2; mt++)
#pragma unroll
                for (int nt = 0; nt < NTT; nt++)
                    mma16816(acc[mt][nt], a[mt], b[nt]);
        }
        __syncthreads();
        if (++stage == 3) stage = 0;
    }
#undef ISSUE

    if (EPI == 2) {
        __nv_bfloat16* Cb = (__nv_bfloat16*)Cv + (size_t)blockIdx.z * strC;
#pragma unroll
        for (int mt = 0; mt < 2; mt++)
#pragma unroll
            for (int nt = 0; nt < NTT; nt++) {
                int m = row0 + wm * 32 + mt * 16 + (lane >> 2);
                int n = col0 + wn * (NT / 2) + nt * 8 + 2 * (lane & 3);
#pragma unroll
                for (int rr = 0; rr < 2; rr++) {
                    int mr = m + rr * 8;
                    float v0 = acc[mt][nt][rr * 2], v1 = acc[mt][nt][rr * 2 + 1];
                    __nv_bfloat16 h0, l0, h1, l1;
                    bfsplit(v0, h0, l0); bfsplit(v1, h1, l1);
                    size_t base = (size_t)mr * ldc + n;
                    *(__nv_bfloat162*)&Cb[base]        = __nv_bfloat162(h0, h1);
                    *(__nv_bfloat162*)&Cb[base + 1024] = __nv_bfloat162(l0, l1);
                    *(__nv_bfloat162*)&Cb[base + 2048] = __nv_bfloat162(h0, h1);
                }
            }
    } else {
        float* Cf = (float*)Cv + (size_t)blockIdx.z * strC;
#pragma unroll
        for (int mt = 0; mt < 2; mt++)
#pragma unroll
            for (int nt = 0; nt < NTT; nt++) {
                int m = row0 + wm * 32 + mt * 16 + (lane >> 2);
                int n = col0 + wn * (NT / 2) + nt * 8 + 2 * (lane & 3);
                float c0 = acc[mt][nt][0], c1 = acc[mt][nt][1];
                float c2 = acc[mt][nt][2], c3 = acc[mt][nt][3];
                if (EPI == 1) { c0 = tanhf(c0); c1 = tanhf(c1); c2 = tanhf(c2); c3 = tanhf(c3); }
                *(float2*)&Cf[(size_t)m * ldc + n] = make_float2(c0, c1);
                *(float2*)&Cf[(size_t)(m + 8) * ldc + n] = make_float2(c2, c3);
            }
    }
}

// split-K reduction + tanh: out = tanh(p0 + p1)
__global__ void __launch_bounds__(256) reduce_tanh(
    const float* __restrict__ P, float* __restrict__ out)
{
    int i4 = blockIdx.x * 256 + threadIdx.x;   // 262144 float4
    float4 a = *(const float4*)&P[(size_t)i4 * 4];
    float4 b = *(const float4*)&P[(size_t)2048 * 512 + (size_t)i4 * 4];
    float4 o = make_float4(tanhf(a.x + b.x), tanhf(a.y + b.y),
                           tanhf(a.z + b.z), tanhf(a.w + b.w));
    *(float4*)&out[(size_t)i4 * 4] = o;
}

// ---------------------------------------------------------------------------
// Energies + masked softmax; writes attn directly as bf16 split (A-form)
// ---------------------------------------------------------------------------
__global__ void __launch_bounds__(256) attn_energy_softmax(
    const int* __restrict__ lens, const float* __restrict__ v)
{
    __shared__ __align__(16) float sA[4][516];
    __shared__ float sB[256][33];
    __shared__ float sV[HH];
    __shared__ float red[8];

    const int b  = blockIdx.y;
    const int t0 = blockIdx.x << 2;
    const int tid = threadIdx.x;
    const int t_local = tid & 3, sg = tid >> 2;
    const float* WsQ = g_WW;
    const float* WhE = g_WW + (size_t)2048 * 512;

    for (int i = tid; i < 512; i += 256) {
        int row = i >> 7, q = (i & 127) << 2;
        float4 val = *(const float4*)&WsQ[((size_t)(b * TB + t0 + row)) * HH + q];
        sA[row][q + 0] = val.x; sA[row][q + 1] = val.y;
        sA[row][q + 2] = val.z; sA[row][q + 3] = val.w;
    }
    for (int i = tid; i < HH; i += 256) sV[i] = v[i];

    float acc0 = 0.f, acc1 = 0.f, acc2 = 0.f, acc3 = 0.f;
    const int srow = sg << 2;

    for (int hc = 0; hc < 16; hc++) {
        __syncthreads();
        for (int i = tid; i < 2048; i += 256) {
            int row = i >> 3, q = (i & 7) << 2;
            float4 val = *(const float4*)
                &WhE[((size_t)(b * SB + row)) * HH + (hc << 5) + q];
            sB[row][q + 0] = val.x; sB[row][q + 1] = val.y;
            sB[row][q + 2] = val.z; sB[row][q + 3] = val.w;
        }
        __syncthreads();

        const float* ar = &sA[t_local][hc << 5];
        const float* vr = &sV[hc << 5];
        const float* br = &sB[srow][0];
#pragma unroll 8
        for (int hh = 0; hh < 32; hh++) {
            float a = ar[hh], vv = vr[hh];
            acc0 = fmaf(vv, tanhfast(a + br[hh]),      acc0);
            acc1 = fmaf(vv, tanhfast(a + br[33 + hh]), acc1);
            acc2 = fmaf(vv, tanhfast(a + br[66 + hh]), acc2);
            acc3 = fmaf(vv, tanhfast(a + br[99 + hh]), acc3);
        }
    }

    float* eS = &sA[0][0];
    __syncthreads();
    eS[t_local * 260 + srow + 0] = acc0;
    eS[t_local * 260 + srow + 1] = acc1;
    eS[t_local * 260 + srow + 2] = acc2;
    eS[t_local * 260 + srow + 3] = acc3;
    __syncthreads();

    const int r = tid >> 6, k = tid & 63, s0 = k << 2;
    const int len = lens[b];
    float4 ev = *(float4*)(eS + r * 260 + s0);

    float mloc = -3.0e38f;
    if (s0 + 0 < len) mloc = fmaxf(mloc, ev.x);
    if (s0 + 1 < len) mloc = fmaxf(mloc, ev.y);
    if (s0 + 2 < len) mloc = fmaxf(mloc, ev.z);
    if (s0 + 3 < len) mloc = fmaxf(mloc, ev.w);
#pragma unroll
    for (int o = 16; o; o >>= 1) mloc = fmaxf(mloc, __shfl_xor_sync(~0u, mloc, o));
    if ((tid & 31) == 0) red[tid >> 5] = mloc;
    __syncthreads();
    float m = fmaxf(red[2 * r], red[2 * r + 1]);

    float e0 = (s0 + 0 < len) ? __expf(ev.x - m) : 0.f;
    float e1 = (s0 + 1 < len) ? __expf(ev.y - m) : 0.f;
    float e2 = (s0 + 2 < len) ? __expf(ev.z - m) : 0.f;
    float e3 = (s0 + 3 < len) ? __expf(ev.w - m) : 0.f;
    float sloc = e0 + e1 + e2 + e3;
#pragma unroll
    for (int o = 16; o; o >>= 1) sloc += __shfl_xor_sync(~0u, sloc, o);
    __syncthreads();
    if ((tid & 31) == 0) red[tid >> 5] = sloc;
    __syncthreads();
    float inv = 1.f / (red[2 * r] + red[2 * r + 1]);

    float w0 = e0 * inv, w1 = e1 * inv, w2 = e2 * inv, w3 = e3 * inv;
    __nv_bfloat16 h0, l0, h1, l1, h2, l2, h3, l3;
    bfsplit(w0, h0, l0); bfsplit(w1, h1, l1);
    bfsplit(w2, h2, l2); bfsplit(w3, h3, l3);
    size_t rb = ((size_t)(b * TB + t0 + r)) * 768;
    __nv_bfloat162 hA(h0, h1), hB(h2, h3), lA(l0, l1), lB(l2, l3);
    *(__nv_bfloat162*)&g_attnS[rb + s0]           = hA;
    *(__nv_bfloat162*)&g_attnS[rb + s0 + 2]       = hB;
    *(__nv_bfloat162*)&g_attnS[rb + 256 + s0]     = lA;
    *(__nv_bfloat162*)&g_attnS[rb + 256 + s0 + 2] = lB;
    *(__nv_bfloat162*)&g_attnS[rb + 512 + s0]     = hA;
    *(__nv_bfloat162*)&g_attnS[rb + 512 + s0 + 2] = hB;
}

// ---------------------------------------------------------------------------

extern "C" void kernel_launch(void* const* d_in, const int* in_sizes, int n_in,
                              void* d_out, int out_size)
{
    (void)in_sizes; (void)n_in; (void)out_size;
    const float* query = (const float*)d_in[0];
    const float* enc   = (const float*)d_in[1];
    const int*   lens  = (const int*)d_in[2];
    const float* W_s   = (const float*)d_in[3];
    const float* W_h   = (const float*)d_in[4];
    const float* v     = (const float*)d_in[5];
    const float* W_out = (const float*)d_in[6];
    float* out = (float*)d_out;

    __nv_bfloat16 *pin3, *pW12, *pWo3, *pA5, *pAttnS, *peT;
    float *pWW, *pP5;
    cudaGetSymbolAddress((void**)&pin3, g_in3);
    cudaGetSymbolAddress((void**)&pW12, g_W12);
    cudaGetSymbolAddress((void**)&pWo3, g_Wo3);
    cudaGetSymbolAddress((void**)&pWW, g_WW);
    cudaGetSymbolAddress((void**)&pA5, g_A5);
    cudaGetSymbolAddress((void**)&pAttnS, g_attnS);
    cudaGetSymbolAddress((void**)&peT, g_eT);
    cudaGetSymbolAddress((void**)&pP5, g_P5);

    // conversions
    conv_inputs<<<2048, 256>>>(query, enc);
    conv_weights<<<1024, 256>>>(W_s, W_h, W_out);
    transpose_split_enc<<<dim3(16, 8, 8), 256>>>(enc, peT);

    // 1+2) WsQ / WhE batched (z=2), K'=1536, 128x128 tiles -> 128 CTAs
    hmma_gemm<0, 128><<<dim3(4, 16, 2), 256>>>(pin3, pW12, pWW, 1536, 1536, 512,
                                               (size_t)2048 * 1536, (size_t)512 * 1536,
                                               (size_t)2048 * 512);
    // 3) energies + masked softmax -> attn split bf16
    attn_energy_softmax<<<dim3(64, 8), 256>>>(lens, v);
    // 4) context = attn @ enc (batched, K'=768) -> A5 ctx half (split store)
    hmma_gemm<2, 64><<<dim3(8, 2, 8), 256>>>(pAttnS, peT, pA5, 768, 768, 3072,
                                             (size_t)TB * 768, (size_t)HH * 768,
                                             (size_t)TB * 3072);
    // 5) out GEMM split-K x2: z slices K'=[0,1536) and [1536,3072)
    hmma_gemm<0, 128><<<dim3(4, 16, 2), 256>>>(pA5, pWo3, pP5, 1536, 3072, 512,
                                               (size_t)1536, (size_t)1536,
                                               (size_t)2048 * 512);
    reduce_tanh<<<1024, 256>>>(pP5, out);
}